// round 12
// baseline (speedup 1.0000x reference)
#include <cuda_runtime.h>
#include <cuda_bf16.h>
#include <math.h>
#include <math_constants.h>
#include <cstdint>

// Problem shapes (fixed by the dataset)
#define B_ 64
#define C_ 5
#define H_ 50
#define S_ 32
#define E_ 768
#define D_ 768
#define K_ 5
#define CROWS (B_*C_)            // 320 candidate rows
#define HROWS (B_*H_)            // 3200 history rows
#define ROWS (CROWS + HROWS)     // 3520 total projected rows
#define ROWSP 3584               // padded to multiple of 128
#define SEL (CROWS*K_)           // 1600 gather selections
#define SE (S_*E_)               // 24576 floats per selection

// Hybrid GEMM row partition
#define MT_ROWS 2048             // rows done by tensor path (16 x 128-tiles)
#define MF_ROWS (ROWSP - MT_ROWS)       // 1536 rows via FFMA (24 x 64-tiles)
#define NCTA_T (MT_ROWS/128 * (D_/128)) // 96
#define NCTA_F (MF_ROWS/64  * (D_/64))  // 288

// ---------------- scratch (static device globals; no allocation) -----------
__device__ __nv_bfloat16 g_Xs[3][(size_t)MT_ROWS * D_];  // X split limbs (tensor rows only)
__device__ __nv_bfloat16 g_Ws[3][(size_t)D_ * D_];       // W split limbs
__device__ float  g_P[(size_t)ROWSP * D_];               // projected rows (padded)
__device__ int    g_idx[SEL];                            // top-K indices per (b,c)

// ======================= small helpers =====================================
__device__ __forceinline__ uint32_t smem_u32(const void* p) {
    uint32_t a;
    asm("{ .reg .u64 t; cvta.to.shared.u64 t, %1; cvt.u32.u64 %0, t; }" : "=r"(a) : "l"(p));
    return a;
}
__device__ __forceinline__ void cp_async16(uint32_t dst, const void* src) {
    asm volatile("cp.async.cg.shared.global [%0], [%1], 16;"
                 :: "r"(dst), "l"(__cvta_generic_to_global(src)));
}
#define CP_COMMIT() asm volatile("cp.async.commit_group;" ::: "memory")
#define CP_WAIT(n)  asm volatile("cp.async.wait_group %0;" :: "n"(n) : "memory")

__device__ __forceinline__ void ldsm4(uint32_t addr, uint32_t& r0, uint32_t& r1,
                                      uint32_t& r2, uint32_t& r3) {
    asm volatile("ldmatrix.sync.aligned.m8n8.x4.shared.b16 {%0,%1,%2,%3}, [%4];"
                 : "=r"(r0), "=r"(r1), "=r"(r2), "=r"(r3) : "r"(addr));
}
__device__ __forceinline__ void mma16816(float* c, const uint32_t* a,
                                         uint32_t b0, uint32_t b1) {
    asm volatile("mma.sync.aligned.m16n8k16.row.col.f32.bf16.bf16.f32 "
                 "{%0,%1,%2,%3}, {%4,%5,%6,%7}, {%8,%9}, {%0,%1,%2,%3};"
                 : "+f"(c[0]), "+f"(c[1]), "+f"(c[2]), "+f"(c[3])
                 : "r"(a[0]), "r"(a[1]), "r"(a[2]), "r"(a[3]), "r"(b0), "r"(b1));
}
__device__ __forceinline__ uint32_t pack_bf2(float lo, float hi) {
    __nv_bfloat162 t = __floats2bfloat162_rn(lo, hi);
    return *(uint32_t*)&t;
}
__device__ __forceinline__ float bf_trunc(float v, float& rem) {
    __nv_bfloat16 b = __float2bfloat16(v);
    float f = __bfloat162float(b);
    rem = v - f;
    return f;
}

// ================== 0a) split X fp32 -> 3 bf16 limbs =======================
__global__ void splitX_kernel(const float* __restrict__ cdd,
                              const float* __restrict__ his) {
    const size_t NX4 = (size_t)MT_ROWS * D_ / 4;
    size_t i = (size_t)blockIdx.x * blockDim.x + threadIdx.x;
    if (i >= NX4) return;
    const size_t base = i * 4;
    const size_t row = base / D_;
    float4 v = (row < CROWS) ? *(const float4*)(cdd + base)
                             : *(const float4*)(his + (base - (size_t)CROWS * D_));
    float f[4] = {v.x, v.y, v.z, v.w};
    #pragma unroll
    for (int lb = 0; lb < 3; lb++) {
        float t[4];
        #pragma unroll
        for (int j = 0; j < 4; j++) { float r; t[j] = bf_trunc(f[j], r); f[j] = r; }
        *(uint2*)&g_Xs[lb][base] = make_uint2(pack_bf2(t[0], t[1]), pack_bf2(t[2], t[3]));
    }
}

// ================== 0b) split W fp32 -> 3 bf16 limbs =======================
__global__ void splitW_kernel(const float* __restrict__ W) {
    const size_t NW4 = (size_t)D_ * D_ / 4;
    size_t i = (size_t)blockIdx.x * blockDim.x + threadIdx.x;
    if (i >= NW4) return;
    const size_t base = i * 4;
    float4 v = *(const float4*)(W + base);
    float f[4] = {v.x, v.y, v.z, v.w};
    #pragma unroll
    for (int lb = 0; lb < 3; lb++) {
        float t[4];
        #pragma unroll
        for (int j = 0; j < 4; j++) { float r; t[j] = bf_trunc(f[j], r); f[j] = r; }
        *(uint2*)&g_Ws[lb][base] = make_uint2(pack_bf2(t[0], t[1]), pack_bf2(t[2], t[3]));
    }
}

// =========== 1) HYBRID GEMM: tensor path (rows<2048) + FFMA path ===========
// UNCHANGED from R10 (proven 257us composite, rel_err 0.0).
#define NPROD 6
#define KC 32
#define NKT (D_ / KC)                    // 24
#define NIT (NPROD * NKT)                // 144
#define SSTRIDE 40

__constant__ int c_pa[NPROD] = {0, 0, 1, 0, 2, 1};
__constant__ int c_pb[NPROD] = {0, 1, 0, 2, 0, 1};

#define SM_BYTES 40960

__global__ void __launch_bounds__(256, 2)
gemm_hybrid(const float* __restrict__ cdd, const float* __restrict__ his,
            const float* __restrict__ W, const float* __restrict__ bias) {
    __shared__ __align__(16) unsigned char smraw[SM_BYTES];

    const int tid  = threadIdx.x;

    if (blockIdx.x < NCTA_T) {
        // ----------------- tensor path (rows 0..2047) ----------------------
        const int bt = blockIdx.x;
        const int m0 = (bt % (MT_ROWS / 128)) * 128;
        const int n0 = (bt / (MT_ROWS / 128)) * 128;
        const int wid = tid >> 5, lane = tid & 31;
        const int wm = (wid >> 2) * 64;
        const int wn = (wid & 3) * 32;

        const uint32_t base = smem_u32(smraw);
        const uint32_t sAb[2] = { base,         base + 10240 };
        const uint32_t sBb[2] = { base + 20480, base + 30720 };

        const int jrow[2] = { tid >> 2, (tid + 256) >> 2 };
        const int jq  = tid & 3;

        float acc[4][4][4];
        #pragma unroll
        for (int i = 0; i < 4; i++)
            #pragma unroll
            for (int j = 0; j < 4; j++)
                #pragma unroll
                for (int v = 0; v < 4; v++) acc[i][j][v] = 0.f;

        auto load_tile = [&](int it, int buf) {
            const int p  = it / NKT;
            const int kb = (it % NKT) * KC;
            const __nv_bfloat16* Asrc = g_Xs[c_pa[p]];
            const __nv_bfloat16* Bsrc = g_Ws[c_pb[p]];
            #pragma unroll
            for (int h = 0; h < 2; h++) {
                const int row = jrow[h];
                cp_async16(sAb[buf] + (uint32_t)(row * SSTRIDE + jq * 8) * 2,
                           Asrc + (size_t)(m0 + row) * D_ + kb + jq * 8);
                cp_async16(sBb[buf] + (uint32_t)(row * SSTRIDE + jq * 8) * 2,
                           Bsrc + (size_t)(n0 + row) * D_ + kb + jq * 8);
            }
            CP_COMMIT();
        };

        load_tile(0, 0);
        const int lrow = lane & 15;
        const int lcol = (lane >> 4) << 3;

        for (int it = 0; it < NIT; it++) {
            const int buf = it & 1;
            if (it + 1 < NIT) { load_tile(it + 1, buf ^ 1); CP_WAIT(1); }
            else              { CP_WAIT(0); }
            __syncthreads();

            #pragma unroll
            for (int kh = 0; kh < 2; kh++) {
                const int kb = kh * 16;
                uint32_t a[4][4];
                #pragma unroll
                for (int mf = 0; mf < 4; mf++) {
                    uint32_t addr = sAb[buf] +
                        (uint32_t)((wm + mf * 16 + lrow) * SSTRIDE + kb + lcol) * 2;
                    ldsm4(addr, a[mf][0], a[mf][1], a[mf][2], a[mf][3]);
                }
                uint32_t bfr[2][4];
                #pragma unroll
                for (int nb = 0; nb < 2; nb++) {
                    uint32_t addr = sBb[buf] +
                        (uint32_t)((wn + nb * 16 + lrow) * SSTRIDE + kb + lcol) * 2;
                    ldsm4(addr, bfr[nb][0], bfr[nb][1], bfr[nb][2], bfr[nb][3]);
                }
                #pragma unroll
                for (int mf = 0; mf < 4; mf++)
                    #pragma unroll
                    for (int oct = 0; oct < 4; oct++) {
                        const int nb = oct >> 1, par = oct & 1;
                        mma16816(acc[mf][oct], a[mf], bfr[nb][par], bfr[nb][par + 2]);
                    }
            }
            __syncthreads();
        }

        const int g = lane >> 2, t = lane & 3;
        #pragma unroll
        for (int mf = 0; mf < 4; mf++) {
            #pragma unroll
            for (int oct = 0; oct < 4; oct++) {
                const int col = n0 + wn + oct * 8 + 2 * t;
                const float b0 = __ldg(bias + col), b1 = __ldg(bias + col + 1);
                const int r0 = m0 + wm + mf * 16 + g;
                float2 v0 = { acc[mf][oct][0] + b0, acc[mf][oct][1] + b1 };
                float2 v1 = { acc[mf][oct][2] + b0, acc[mf][oct][3] + b1 };
                *(float2*)(g_P + (size_t)r0 * D_ + col)       = v0;
                *(float2*)(g_P + (size_t)(r0 + 8) * D_ + col) = v1;
            }
        }
    } else {
        // ----------------- FFMA path (rows 2048..3583), exact R1 -----------
        const int bf = blockIdx.x - NCTA_T;
        const int m0 = MT_ROWS + (bf % (MF_ROWS / 64)) * 64;
        const int n0 = (bf / (MF_ROWS / 64)) * 64;

        float (*As)[64] = (float(*)[64])smraw;          // [16][64]
        float (*Bs)[64] = (float(*)[64])(smraw + 4096); // [16][64]

        const int tx = tid & 15, ty = tid >> 4;
        const int lrow = tid >> 2;
        const int kq   = (tid & 3) << 2;
        const int gr   = m0 + lrow;
        const float* xsrc = (gr < CROWS) ? (cdd + (size_t)gr * D_)
                         : (gr < ROWS)   ? (his + (size_t)(gr - CROWS) * D_)
                                         : his;
        const float* wsrc = W + (size_t)(n0 + lrow) * D_;

        float acc[4][4] = {};

        for (int k0 = 0; k0 < D_; k0 += 16) {
            float4 a = *(const float4*)(xsrc + k0 + kq);
            float4 b = *(const float4*)(wsrc + k0 + kq);
            As[kq+0][lrow] = a.x; As[kq+1][lrow] = a.y;
            As[kq+2][lrow] = a.z; As[kq+3][lrow] = a.w;
            Bs[kq+0][lrow] = b.x; Bs[kq+1][lrow] = b.y;
            Bs[kq+2][lrow] = b.z; Bs[kq+3][lrow] = b.w;
            __syncthreads();

            #pragma unroll
            for (int kk = 0; kk < 16; kk++) {
                float4 av = *(const float4*)&As[kk][ty << 2];
                float4 bv = *(const float4*)&Bs[kk][tx << 2];
                float aa[4] = {av.x, av.y, av.z, av.w};
                float bb[4] = {bv.x, bv.y, bv.z, bv.w};
                #pragma unroll
                for (int i = 0; i < 4; i++)
                    #pragma unroll
                    for (int j = 0; j < 4; j++)
                        acc[i][j] = fmaf(aa[i], bb[j], acc[i][j]);
            }
            __syncthreads();
        }

        #pragma unroll
        for (int i = 0; i < 4; i++) {
            const int r = m0 + (ty << 2) + i;
            #pragma unroll
            for (int j = 0; j < 4; j++) {
                const int n = n0 + (tx << 2) + j;
                g_P[(size_t)r * D_ + n] = acc[i][j] + bias[n];
            }
        }
    }
}

// =============== compensated fp32 accumulation (TwoProd+TwoSum) ============
__device__ __forceinline__ void dot2_acc(float a, float b, float& s, float& c) {
    float p  = __fmul_rn(a, b);
    float e  = __fmaf_rn(a, b, -p);
    float t  = __fadd_rn(s, p);
    float bp = __fsub_rn(t, s);
    float e2 = __fadd_rn(__fsub_rn(s, __fsub_rn(t, bp)), __fsub_rn(p, bp));
    s = t;
    c = __fadd_rn(c, __fadd_rn(e, e2));
}

// ---------- 2+3+4) fused norms + attention + top-K; 512 thr (16 warps) ----
// Per-(c,h) arithmetic bit-identical to R10 — only h->warp schedule changed.
__global__ void __launch_bounds__(512, 1)
attn_topk(const int* __restrict__ his_mask) {
    const int b = blockIdx.x;
    const int tid = threadIdx.x;
    const int w = tid >> 5, l = tid & 31;

    __shared__ float  cand[C_][D_];      // 15 KB
    __shared__ double invc[C_];
    __shared__ double sc[C_][64];        // scores, padded to 64

    for (int i = tid; i < C_ * (D_ / 4); i += 512) {
        const int c = i / (D_ / 4), j = i % (D_ / 4);
        ((float4*)cand[c])[j] = ((const float4*)(g_P + (size_t)(b * C_ + c) * D_))[j];
    }
    for (int i = tid; i < C_ * 64; i += 512) ((double*)sc)[i] = -CUDART_INF;
    __syncthreads();

    if (w < C_) {
        float s = 0.f, cc = 0.f;
        for (int k = l; k < D_; k += 32) { float v = cand[w][k]; dot2_acc(v, v, s, cc); }
        double d = (double)s + (double)cc;
        #pragma unroll
        for (int o = 16; o; o >>= 1) d += __shfl_down_sync(0xffffffffu, d, o);
        if (l == 0) invc[w] = 1.0 / fmax(sqrt(d), 1e-12);
    }
    __syncthreads();

    for (int h = w; h < H_; h += 16) {
        const float4* ph = (const float4*)(g_P + (size_t)(CROWS + b * H_ + h) * D_);
        float s[C_] = {}, cc[C_] = {};
        float sn = 0.f, cn = 0.f;
        #pragma unroll
        for (int j = 0; j < D_ / 128; j++) {
            const int idx = l + 32 * j;
            const float4 v = ph[idx];
            dot2_acc(v.x, v.x, sn, cn); dot2_acc(v.y, v.y, sn, cn);
            dot2_acc(v.z, v.z, sn, cn); dot2_acc(v.w, v.w, sn, cn);
            #pragma unroll
            for (int c = 0; c < C_; c++) {
                const float4 cv = ((const float4*)cand[c])[idx];
                dot2_acc(v.x, cv.x, s[c], cc[c]); dot2_acc(v.y, cv.y, s[c], cc[c]);
                dot2_acc(v.z, cv.z, s[c], cc[c]); dot2_acc(v.w, cv.w, s[c], cc[c]);
            }
        }
        double dn = (double)sn + (double)cn;
        double dc[C_];
        #pragma unroll
        for (int c = 0; c < C_; c++) dc[c] = (double)s[c] + (double)cc[c];
        #pragma unroll
        for (int o = 16; o; o >>= 1) {
            dn += __shfl_down_sync(0xffffffffu, dn, o);
            #pragma unroll
            for (int c = 0; c < C_; c++) dc[c] += __shfl_down_sync(0xffffffffu, dc[c], o);
        }
        if (l == 0) {
            const bool valid = (his_mask[b * H_ + h] != 0) || (h < K_);
            const double invh = 1.0 / fmax(sqrt(dn), 1e-12);
            #pragma unroll
            for (int c = 0; c < C_; c++)
                sc[c][h] = valid ? dc[c] * invc[c] * invh : -CUDART_INF;
        }
    }
    __syncthreads();

    if (w < C_) {
        double v0 = sc[w][l];
        double v1 = sc[w][l + 32];
        bool used0 = false, used1 = false;
        for (int k = 0; k < K_; k++) {
            double bv = -CUDART_INF;
            int    bi = 1 << 30;
            if (!used1)                        { bv = v1; bi = l + 32; }
            if (!used0 && (used1 || v0 >= v1)) { bv = v0; bi = l; }
            #pragma unroll
            for (int o = 16; o; o >>= 1) {
                double ov = __shfl_down_sync(0xffffffffu, bv, o);
                int    oi = __shfl_down_sync(0xffffffffu, bi, o);
                if (ov > bv || (ov == bv && oi < bi)) { bv = ov; bi = oi; }
            }
            bi = __shfl_sync(0xffffffffu, bi, 0);
            if (l == 0) g_idx[(b * C_ + w) * K_ + k] = bi;
            if (bi == l)      used0 = true;
            if (bi == l + 32) used1 = true;
        }
    }
}

// ------- 5+6) embedding gather + fused mask gather (bandwidth-bound) -------
__global__ void gather_emb(const float* __restrict__ emb,
                           const int* __restrict__ am,
                           float* __restrict__ out) {
    const int sel  = blockIdx.x >> 3;
    const int part = blockIdx.x & 7;
    const int b    = sel / (C_ * K_);
    const int idx  = g_idx[sel];
    const float4* src = (const float4*)(emb + ((size_t)b * H_ + idx) * SE);
    float4*       dst = (float4*)(out + (size_t)sel * SE);
    const int base = part * 768;
    #pragma unroll
    for (int i = 0; i < 3; i++) {
        const int o = base + threadIdx.x + i * 256;
        __stcs(dst + o, src[o]);
    }
    if (part == 7 && threadIdx.x < S_) {
        float* outm = out + (size_t)SEL * SE;
        outm[sel * S_ + threadIdx.x] =
            (float)am[((size_t)b * H_ + idx) * S_ + threadIdx.x];
    }
}

// ---------------------------------------------------------------------------
extern "C" void kernel_launch(void* const* d_in, const int* in_sizes, int n_in,
                              void* d_out, int out_size) {
    const float* cdd  = (const float*)d_in[0];   // [B,C,D]
    const float* his  = (const float*)d_in[1];   // [B,H,D]
    const float* emb  = (const float*)d_in[2];   // [B,H,S,E]
    const int*   am   = (const int*)  d_in[3];   // [B,H,S]
    const int*   hm   = (const int*)  d_in[4];   // [B,H,1]
    const float* W    = (const float*)d_in[5];   // [D,D]
    const float* bias = (const float*)d_in[6];   // [D]
    float* out = (float*)d_out;

    const size_t NX4 = (size_t)MT_ROWS * D_ / 4;
    const size_t NW4 = (size_t)D_ * D_ / 4;
    splitX_kernel<<<(unsigned)((NX4 + 255) / 256), 256>>>(cdd, his);
    splitW_kernel<<<(unsigned)((NW4 + 255) / 256), 256>>>(W);
    gemm_hybrid<<<NCTA_T + NCTA_F, 256>>>(cdd, his, W, bias);
    attn_topk<<<B_, 512>>>(hm);
    gather_emb<<<SEL * 8, 256>>>(emb, am, out);
}

// round 13
// speedup vs baseline: 1.0555x; 1.0555x over previous
#include <cuda_runtime.h>
#include <cuda_bf16.h>
#include <math.h>
#include <math_constants.h>
#include <cstdint>

// Problem shapes (fixed by the dataset)
#define B_ 64
#define C_ 5
#define H_ 50
#define S_ 32
#define E_ 768
#define D_ 768
#define K_ 5
#define CROWS (B_*C_)            // 320 candidate rows
#define HROWS (B_*H_)            // 3200 history rows
#define ROWS (CROWS + HROWS)     // 3520 total projected rows
#define ROWSP 3584               // padded to multiple of 128
#define SEL (CROWS*K_)           // 1600 gather selections
#define SE (S_*E_)               // 24576 floats per selection

// Hybrid GEMM row partition
#define MT_ROWS 2048             // rows done by tensor path (16 x 128-tiles)
#define MF_ROWS (ROWSP - MT_ROWS)       // 1536 rows via FFMA (24 x 64-tiles)
#define NCTA_T (MT_ROWS/128 * (D_/128)) // 96
#define NCTA_F (MF_ROWS/64  * (D_/64))  // 288

// ---------------- scratch (static device globals; no allocation) -----------
__device__ __nv_bfloat16 g_Xs[3][(size_t)MT_ROWS * D_];  // X split limbs (tensor rows only)
__device__ __nv_bfloat16 g_Ws[3][(size_t)D_ * D_];       // W split limbs
__device__ float  g_P[(size_t)ROWSP * D_];               // projected rows (padded)
__device__ double g_attn[CROWS * H_];                    // masked attention scores
__device__ int    g_idx[SEL];                            // top-K indices per (b,c)

// ======================= small helpers =====================================
__device__ __forceinline__ uint32_t smem_u32(const void* p) {
    uint32_t a;
    asm("{ .reg .u64 t; cvta.to.shared.u64 t, %1; cvt.u32.u64 %0, t; }" : "=r"(a) : "l"(p));
    return a;
}
__device__ __forceinline__ void cp_async16(uint32_t dst, const void* src) {
    asm volatile("cp.async.cg.shared.global [%0], [%1], 16;"
                 :: "r"(dst), "l"(__cvta_generic_to_global(src)));
}
#define CP_COMMIT() asm volatile("cp.async.commit_group;" ::: "memory")
#define CP_WAIT(n)  asm volatile("cp.async.wait_group %0;" :: "n"(n) : "memory")

__device__ __forceinline__ void ldsm4(uint32_t addr, uint32_t& r0, uint32_t& r1,
                                      uint32_t& r2, uint32_t& r3) {
    asm volatile("ldmatrix.sync.aligned.m8n8.x4.shared.b16 {%0,%1,%2,%3}, [%4];"
                 : "=r"(r0), "=r"(r1), "=r"(r2), "=r"(r3) : "r"(addr));
}
__device__ __forceinline__ void mma16816(float* c, const uint32_t* a,
                                         uint32_t b0, uint32_t b1) {
    asm volatile("mma.sync.aligned.m16n8k16.row.col.f32.bf16.bf16.f32 "
                 "{%0,%1,%2,%3}, {%4,%5,%6,%7}, {%8,%9}, {%0,%1,%2,%3};"
                 : "+f"(c[0]), "+f"(c[1]), "+f"(c[2]), "+f"(c[3])
                 : "r"(a[0]), "r"(a[1]), "r"(a[2]), "r"(a[3]), "r"(b0), "r"(b1));
}
__device__ __forceinline__ uint32_t pack_bf2(float lo, float hi) {
    __nv_bfloat162 t = __floats2bfloat162_rn(lo, hi);
    return *(uint32_t*)&t;
}
__device__ __forceinline__ float bf_trunc(float v, float& rem) {
    __nv_bfloat16 b = __float2bfloat16(v);
    float f = __bfloat162float(b);
    rem = v - f;
    return f;
}

// ================== 0a) split X fp32 -> 3 bf16 limbs =======================
__global__ void splitX_kernel(const float* __restrict__ cdd,
                              const float* __restrict__ his) {
    const size_t NX4 = (size_t)MT_ROWS * D_ / 4;
    size_t i = (size_t)blockIdx.x * blockDim.x + threadIdx.x;
    if (i >= NX4) return;
    const size_t base = i * 4;
    const size_t row = base / D_;
    float4 v = (row < CROWS) ? *(const float4*)(cdd + base)
                             : *(const float4*)(his + (base - (size_t)CROWS * D_));
    float f[4] = {v.x, v.y, v.z, v.w};
    #pragma unroll
    for (int lb = 0; lb < 3; lb++) {
        float t[4];
        #pragma unroll
        for (int j = 0; j < 4; j++) { float r; t[j] = bf_trunc(f[j], r); f[j] = r; }
        *(uint2*)&g_Xs[lb][base] = make_uint2(pack_bf2(t[0], t[1]), pack_bf2(t[2], t[3]));
    }
}

// ================== 0b) split W fp32 -> 3 bf16 limbs =======================
__global__ void splitW_kernel(const float* __restrict__ W) {
    const size_t NW4 = (size_t)D_ * D_ / 4;
    size_t i = (size_t)blockIdx.x * blockDim.x + threadIdx.x;
    if (i >= NW4) return;
    const size_t base = i * 4;
    float4 v = *(const float4*)(W + base);
    float f[4] = {v.x, v.y, v.z, v.w};
    #pragma unroll
    for (int lb = 0; lb < 3; lb++) {
        float t[4];
        #pragma unroll
        for (int j = 0; j < 4; j++) { float r; t[j] = bf_trunc(f[j], r); f[j] = r; }
        *(uint2*)&g_Ws[lb][base] = make_uint2(pack_bf2(t[0], t[1]), pack_bf2(t[2], t[3]));
    }
}

// =========== 1) HYBRID GEMM: tensor path (rows<2048) + FFMA path ===========
// UNCHANGED from R10 (proven, rel_err 0.0).
#define NPROD 6
#define KC 32
#define NKT (D_ / KC)                    // 24
#define NIT (NPROD * NKT)                // 144
#define SSTRIDE 40

__constant__ int c_pa[NPROD] = {0, 0, 1, 0, 2, 1};
__constant__ int c_pb[NPROD] = {0, 1, 0, 2, 0, 1};

#define SM_BYTES 40960

__global__ void __launch_bounds__(256, 2)
gemm_hybrid(const float* __restrict__ cdd, const float* __restrict__ his,
            const float* __restrict__ W, const float* __restrict__ bias) {
    __shared__ __align__(16) unsigned char smraw[SM_BYTES];

    const int tid  = threadIdx.x;

    if (blockIdx.x < NCTA_T) {
        // ----------------- tensor path (rows 0..2047) ----------------------
        const int bt = blockIdx.x;
        const int m0 = (bt % (MT_ROWS / 128)) * 128;
        const int n0 = (bt / (MT_ROWS / 128)) * 128;
        const int wid = tid >> 5, lane = tid & 31;
        const int wm = (wid >> 2) * 64;
        const int wn = (wid & 3) * 32;

        const uint32_t base = smem_u32(smraw);
        const uint32_t sAb[2] = { base,         base + 10240 };
        const uint32_t sBb[2] = { base + 20480, base + 30720 };

        const int jrow[2] = { tid >> 2, (tid + 256) >> 2 };
        const int jq  = tid & 3;

        float acc[4][4][4];
        #pragma unroll
        for (int i = 0; i < 4; i++)
            #pragma unroll
            for (int j = 0; j < 4; j++)
                #pragma unroll
                for (int v = 0; v < 4; v++) acc[i][j][v] = 0.f;

        auto load_tile = [&](int it, int buf) {
            const int p  = it / NKT;
            const int kb = (it % NKT) * KC;
            const __nv_bfloat16* Asrc = g_Xs[c_pa[p]];
            const __nv_bfloat16* Bsrc = g_Ws[c_pb[p]];
            #pragma unroll
            for (int h = 0; h < 2; h++) {
                const int row = jrow[h];
                cp_async16(sAb[buf] + (uint32_t)(row * SSTRIDE + jq * 8) * 2,
                           Asrc + (size_t)(m0 + row) * D_ + kb + jq * 8);
                cp_async16(sBb[buf] + (uint32_t)(row * SSTRIDE + jq * 8) * 2,
                           Bsrc + (size_t)(n0 + row) * D_ + kb + jq * 8);
            }
            CP_COMMIT();
        };

        load_tile(0, 0);
        const int lrow = lane & 15;
        const int lcol = (lane >> 4) << 3;

        for (int it = 0; it < NIT; it++) {
            const int buf = it & 1;
            if (it + 1 < NIT) { load_tile(it + 1, buf ^ 1); CP_WAIT(1); }
            else              { CP_WAIT(0); }
            __syncthreads();

            #pragma unroll
            for (int kh = 0; kh < 2; kh++) {
                const int kb = kh * 16;
                uint32_t a[4][4];
                #pragma unroll
                for (int mf = 0; mf < 4; mf++) {
                    uint32_t addr = sAb[buf] +
                        (uint32_t)((wm + mf * 16 + lrow) * SSTRIDE + kb + lcol) * 2;
                    ldsm4(addr, a[mf][0], a[mf][1], a[mf][2], a[mf][3]);
                }
                uint32_t bfr[2][4];
                #pragma unroll
                for (int nb = 0; nb < 2; nb++) {
                    uint32_t addr = sBb[buf] +
                        (uint32_t)((wn + nb * 16 + lrow) * SSTRIDE + kb + lcol) * 2;
                    ldsm4(addr, bfr[nb][0], bfr[nb][1], bfr[nb][2], bfr[nb][3]);
                }
                #pragma unroll
                for (int mf = 0; mf < 4; mf++)
                    #pragma unroll
                    for (int oct = 0; oct < 4; oct++) {
                        const int nb = oct >> 1, par = oct & 1;
                        mma16816(acc[mf][oct], a[mf], bfr[nb][par], bfr[nb][par + 2]);
                    }
            }
            __syncthreads();
        }

        const int g = lane >> 2, t = lane & 3;
        #pragma unroll
        for (int mf = 0; mf < 4; mf++) {
            #pragma unroll
            for (int oct = 0; oct < 4; oct++) {
                const int col = n0 + wn + oct * 8 + 2 * t;
                const float b0 = __ldg(bias + col), b1 = __ldg(bias + col + 1);
                const int r0 = m0 + wm + mf * 16 + g;
                float2 v0 = { acc[mf][oct][0] + b0, acc[mf][oct][1] + b1 };
                float2 v1 = { acc[mf][oct][2] + b0, acc[mf][oct][3] + b1 };
                *(float2*)(g_P + (size_t)r0 * D_ + col)       = v0;
                *(float2*)(g_P + (size_t)(r0 + 8) * D_ + col) = v1;
            }
        }
    } else {
        // ----------------- FFMA path (rows 2048..3583), exact R1 -----------
        const int bf = blockIdx.x - NCTA_T;
        const int m0 = MT_ROWS + (bf % (MF_ROWS / 64)) * 64;
        const int n0 = (bf / (MF_ROWS / 64)) * 64;

        float (*As)[64] = (float(*)[64])smraw;          // [16][64]
        float (*Bs)[64] = (float(*)[64])(smraw + 4096); // [16][64]

        const int tx = tid & 15, ty = tid >> 4;
        const int lrow = tid >> 2;
        const int kq   = (tid & 3) << 2;
        const int gr   = m0 + lrow;
        const float* xsrc = (gr < CROWS) ? (cdd + (size_t)gr * D_)
                         : (gr < ROWS)   ? (his + (size_t)(gr - CROWS) * D_)
                                         : his;
        const float* wsrc = W + (size_t)(n0 + lrow) * D_;

        float acc[4][4] = {};

        for (int k0 = 0; k0 < D_; k0 += 16) {
            float4 a = *(const float4*)(xsrc + k0 + kq);
            float4 b = *(const float4*)(wsrc + k0 + kq);
            As[kq+0][lrow] = a.x; As[kq+1][lrow] = a.y;
            As[kq+2][lrow] = a.z; As[kq+3][lrow] = a.w;
            Bs[kq+0][lrow] = b.x; Bs[kq+1][lrow] = b.y;
            Bs[kq+2][lrow] = b.z; Bs[kq+3][lrow] = b.w;
            __syncthreads();

            #pragma unroll
            for (int kk = 0; kk < 16; kk++) {
                float4 av = *(const float4*)&As[kk][ty << 2];
                float4 bv = *(const float4*)&Bs[kk][tx << 2];
                float aa[4] = {av.x, av.y, av.z, av.w};
                float bb[4] = {bv.x, bv.y, bv.z, bv.w};
                #pragma unroll
                for (int i = 0; i < 4; i++)
                    #pragma unroll
                    for (int j = 0; j < 4; j++)
                        acc[i][j] = fmaf(aa[i], bb[j], acc[i][j]);
            }
            __syncthreads();
        }

        #pragma unroll
        for (int i = 0; i < 4; i++) {
            const int r = m0 + (ty << 2) + i;
            #pragma unroll
            for (int j = 0; j < 4; j++) {
                const int n = n0 + (tx << 2) + j;
                g_P[(size_t)r * D_ + n] = acc[i][j] + bias[n];
            }
        }
    }
}

// =============== compensated fp32 accumulation (TwoProd+TwoSum) ============
__device__ __forceinline__ void dot2_acc(float a, float b, float& s, float& c) {
    float p  = __fmul_rn(a, b);
    float e  = __fmaf_rn(a, b, -p);
    float t  = __fadd_rn(s, p);
    float bp = __fsub_rn(t, s);
    float e2 = __fadd_rn(__fsub_rn(s, __fsub_rn(t, bp)), __fsub_rn(p, bp));
    s = t;
    c = __fadd_rn(c, __fadd_rn(e, e2));
}

// ---------- 2+3) attention scores, block (b, part): h in [10p, 10p+10) -----
// Per-(c,h) score arithmetic bit-identical to R10/R11; candidate norms
// recomputed per block (identical inputs+order => identical values).
#define HSPLIT 5
#define HPER (H_ / HSPLIT)               // 10

__global__ void __launch_bounds__(256)
attn_score(const int* __restrict__ his_mask) {
    const int b    = blockIdx.x;
    const int part = blockIdx.y;
    const int tid = threadIdx.x;
    const int w = tid >> 5, l = tid & 31;

    __shared__ float  cand[C_][D_];      // 15 KB
    __shared__ double invc[C_];

    for (int i = tid; i < C_ * (D_ / 4); i += 256) {
        const int c = i / (D_ / 4), j = i % (D_ / 4);
        ((float4*)cand[c])[j] = ((const float4*)(g_P + (size_t)(b * C_ + c) * D_))[j];
    }
    __syncthreads();

    if (w < C_) {
        float s = 0.f, cc = 0.f;
        for (int k = l; k < D_; k += 32) { float v = cand[w][k]; dot2_acc(v, v, s, cc); }
        double d = (double)s + (double)cc;
        #pragma unroll
        for (int o = 16; o; o >>= 1) d += __shfl_down_sync(0xffffffffu, d, o);
        if (l == 0) invc[w] = 1.0 / fmax(sqrt(d), 1e-12);
    }
    __syncthreads();

    for (int hh = w; hh < HPER; hh += 8) {
        const int h = part * HPER + hh;
        const float4* ph = (const float4*)(g_P + (size_t)(CROWS + b * H_ + h) * D_);
        float s[C_] = {}, cc[C_] = {};
        float sn = 0.f, cn = 0.f;
        #pragma unroll
        for (int j = 0; j < D_ / 128; j++) {
            const int idx = l + 32 * j;
            const float4 v = ph[idx];
            dot2_acc(v.x, v.x, sn, cn); dot2_acc(v.y, v.y, sn, cn);
            dot2_acc(v.z, v.z, sn, cn); dot2_acc(v.w, v.w, sn, cn);
            #pragma unroll
            for (int c = 0; c < C_; c++) {
                const float4 cv = ((const float4*)cand[c])[idx];
                dot2_acc(v.x, cv.x, s[c], cc[c]); dot2_acc(v.y, cv.y, s[c], cc[c]);
                dot2_acc(v.z, cv.z, s[c], cc[c]); dot2_acc(v.w, cv.w, s[c], cc[c]);
            }
        }
        double dn = (double)sn + (double)cn;
        double dc[C_];
        #pragma unroll
        for (int c = 0; c < C_; c++) dc[c] = (double)s[c] + (double)cc[c];
        #pragma unroll
        for (int o = 16; o; o >>= 1) {
            dn += __shfl_down_sync(0xffffffffu, dn, o);
            #pragma unroll
            for (int c = 0; c < C_; c++) dc[c] += __shfl_down_sync(0xffffffffu, dc[c], o);
        }
        if (l == 0) {
            const bool valid = (his_mask[b * H_ + h] != 0) || (h < K_);
            const double invh = 1.0 / fmax(sqrt(dn), 1e-12);
            #pragma unroll
            for (int c = 0; c < C_; c++)
                g_attn[(b * C_ + c) * H_ + h] =
                    valid ? dc[c] * invc[c] * invh : -CUDART_INF;
        }
    }
}

// ---------------- 4) top-K (exact R1 kernel: one warp per (b,c)) -----------
__global__ void topk_kernel() {
    const int gw = (blockIdx.x * blockDim.x + threadIdx.x) >> 5;
    const int l  = threadIdx.x & 31;
    if (gw >= CROWS) return;
    const double* a = g_attn + (size_t)gw * H_;

    double v0 = (l      < H_) ? a[l]      : -CUDART_INF;
    double v1 = (l + 32 < H_) ? a[l + 32] : -CUDART_INF;
    bool used0 = false, used1 = false;

    for (int k = 0; k < K_; k++) {
        double bv = -CUDART_INF;
        int    bi = 1 << 30;
        if (!used1)                           { bv = v1; bi = l + 32; }
        if (!used0 && (used1 || v0 >= v1))    { bv = v0; bi = l; }
        #pragma unroll
        for (int o = 16; o; o >>= 1) {
            double ov = __shfl_down_sync(0xffffffffu, bv, o);
            int    oi = __shfl_down_sync(0xffffffffu, bi, o);
            if (ov > bv || (ov == bv && oi < bi)) { bv = ov; bi = oi; }
        }
        bi = __shfl_sync(0xffffffffu, bi, 0);
        if (l == 0) g_idx[gw * K_ + k] = bi;
        if (bi == l)      used0 = true;
        if (bi == l + 32) used1 = true;
    }
}

// ------- 5+6) embedding gather + fused mask gather (bandwidth-bound) -------
__global__ void gather_emb(const float* __restrict__ emb,
                           const int* __restrict__ am,
                           float* __restrict__ out) {
    const int sel  = blockIdx.x >> 3;
    const int part = blockIdx.x & 7;
    const int b    = sel / (C_ * K_);
    const int idx  = g_idx[sel];
    const float4* src = (const float4*)(emb + ((size_t)b * H_ + idx) * SE);
    float4*       dst = (float4*)(out + (size_t)sel * SE);
    const int base = part * 768;
    #pragma unroll
    for (int i = 0; i < 3; i++) {
        const int o = base + threadIdx.x + i * 256;
        __stcs(dst + o, src[o]);
    }
    if (part == 7 && threadIdx.x < S_) {
        float* outm = out + (size_t)SEL * SE;
        outm[sel * S_ + threadIdx.x] =
            (float)am[((size_t)b * H_ + idx) * S_ + threadIdx.x];
    }
}

// ---------------------------------------------------------------------------
extern "C" void kernel_launch(void* const* d_in, const int* in_sizes, int n_in,
                              void* d_out, int out_size) {
    const float* cdd  = (const float*)d_in[0];   // [B,C,D]
    const float* his  = (const float*)d_in[1];   // [B,H,D]
    const float* emb  = (const float*)d_in[2];   // [B,H,S,E]
    const int*   am   = (const int*)  d_in[3];   // [B,H,S]
    const int*   hm   = (const int*)  d_in[4];   // [B,H,1]
    const float* W    = (const float*)d_in[5];   // [D,D]
    const float* bias = (const float*)d_in[6];   // [D]
    float* out = (float*)d_out;

    const size_t NX4 = (size_t)MT_ROWS * D_ / 4;
    const size_t NW4 = (size_t)D_ * D_ / 4;
    splitX_kernel<<<(unsigned)((NX4 + 255) / 256), 256>>>(cdd, his);
    splitW_kernel<<<(unsigned)((NW4 + 255) / 256), 256>>>(W);
    gemm_hybrid<<<NCTA_T + NCTA_F, 256>>>(cdd, his, W, bias);
    attn_score<<<dim3(B_, HSPLIT), 256>>>(hm);
    topk_kernel<<<(CROWS * 32 + 255) / 256, 256>>>();
    gather_emb<<<SEL * 8, 256>>>(emb, am, out);
}